// round 3
// baseline (speedup 1.0000x reference)
#include <cuda_runtime.h>

// RoiPoolingConv: ROI-Align bilinear pooling, POOL=7
// img:  (8, 64, 64, 1024) float32, NHWC (channels contiguous)
// rois: (32, 4) int32  [x, y, w, h]
// out:  flat index ((r*8 + b)*7 + py)*7 + px, 1024 channels contiguous
//
// R3: persistent grid-stride kernel with 2-stage register pipeline —
// next tile's 4 LDG.128 issued before current tile's lerp+store, keeping
// DRAM continuously busy (no per-CTA launch/drain bubbles).

#define N_ROIS 32
#define N_BATCH 8
#define POOLP 7
#define CH 1024
#define IMG_W 64
#define IMG_H 64
#define N_TILES (N_ROIS * N_BATCH * POOLP * POOLP)   // 12544
#define GRID_CTAS 1184                               // 148 SMs * 8

struct TileAddr {
    const float4* p00;
    const float4* p01;
    const float4* p10;
    const float4* p11;
    float wx, wy;
};

__device__ __forceinline__ TileAddr tile_addr(const float* __restrict__ img,
                                              const int* __restrict__ rois,
                                              int flat)
{
    const int px = flat % POOLP;
    const int py = (flat / POOLP) % POOLP;
    const int b  = (flat / (POOLP * POOLP)) % N_BATCH;
    const int r  = flat / (POOLP * POOLP * N_BATCH);

    const int rx = rois[r * 4 + 0];
    const int ry = rois[r * 4 + 1];
    const int rw = rois[r * 4 + 2];
    const int rh = rois[r * 4 + 3];

    // coord = (p+0.5)*(size/POOL) - 0.5 (matches reference _edge)
    const float cx = ((float)px + 0.5f) * ((float)rw / (float)POOLP) - 0.5f;
    const float fx = floorf(cx);
    const int lox = max((int)fx, 0);
    const int hix = min(max((int)ceilf(cx), 0), rw - 1);
    const int x0 = rx + lox;
    const int x1 = rx + hix;

    const float cy = ((float)py + 0.5f) * ((float)rh / (float)POOLP) - 0.5f;
    const float fy = floorf(cy);
    const int loy = max((int)fy, 0);
    const int hiy = min(max((int)ceilf(cy), 0), rh - 1);
    const int y0 = ry + loy;
    const int y1 = ry + hiy;

    const size_t base_b = (size_t)b * IMG_H * IMG_W * CH;

    TileAddr ta;
    ta.p00 = (const float4*)(img + base_b + ((size_t)y0 * IMG_W + x0) * CH);
    ta.p01 = (const float4*)(img + base_b + ((size_t)y0 * IMG_W + x1) * CH);
    ta.p10 = (const float4*)(img + base_b + ((size_t)y1 * IMG_W + x0) * CH);
    ta.p11 = (const float4*)(img + base_b + ((size_t)y1 * IMG_W + x1) * CH);
    ta.wx = cx - fx;
    ta.wy = cy - fy;
    return ta;
}

__device__ __forceinline__ float4 lerp4(float4 a, float4 b, float4 c, float4 d,
                                        float wx, float wy)
{
    float4 res;
    float top, bot;
    top = a.x + (b.x - a.x) * wx;
    bot = c.x + (d.x - c.x) * wx;
    res.x = top + (bot - top) * wy;
    top = a.y + (b.y - a.y) * wx;
    bot = c.y + (d.y - c.y) * wx;
    res.y = top + (bot - top) * wy;
    top = a.z + (b.z - a.z) * wx;
    bot = c.z + (d.z - c.z) * wx;
    res.z = top + (bot - top) * wy;
    top = a.w + (b.w - a.w) * wx;
    bot = c.w + (d.w - c.w) * wx;
    res.w = top + (bot - top) * wy;
    return res;
}

__global__ void __launch_bounds__(256) roi_align_persist(
    const float* __restrict__ img,
    const int*   __restrict__ rois,
    float*       __restrict__ out)
{
    const int t = threadIdx.x;          // 256 threads * float4 = 1024 channels

    int tile = blockIdx.x;
    if (tile >= N_TILES) return;

    // Prologue: issue loads for first tile
    TileAddr ta = tile_addr(img, rois, tile);
    float4 a = ta.p00[t];
    float4 b = ta.p01[t];
    float4 c = ta.p10[t];
    float4 d = ta.p11[t];

    for (;;) {
        const int next = tile + GRID_CTAS;
        const bool more = next < N_TILES;

        TileAddr tn;
        float4 a2, b2, c2, d2;
        if (more) {
            // Issue next tile's loads BEFORE consuming current tile's data:
            // these 4 LDG.128 overlap the lerp + STG below.
            tn = tile_addr(img, rois, next);
            a2 = tn.p00[t];
            b2 = tn.p01[t];
            c2 = tn.p10[t];
            d2 = tn.p11[t];
        }

        ((float4*)(out + (size_t)tile * CH))[t] =
            lerp4(a, b, c, d, ta.wx, ta.wy);

        if (!more) break;
        tile = next;
        ta = tn;
        a = a2; b = b2; c = c2; d = d2;
    }
}

extern "C" void kernel_launch(void* const* d_in, const int* in_sizes, int n_in,
                              void* d_out, int out_size)
{
    const float* img  = (const float*)d_in[0];
    const int*   rois = (const int*)d_in[1];
    float*       out  = (float*)d_out;

    roi_align_persist<<<GRID_CTAS, 256>>>(img, rois, out);
}

// round 4
// speedup vs baseline: 1.1333x; 1.1333x over previous
#include <cuda_runtime.h>

// RoiPoolingConv: ROI-Align bilinear pooling, POOL=7
// img:  (8, 64, 64, 1024) float32, NHWC (channels contiguous)
// rois: (32, 4) int32  [x, y, w, h]
// out:  flat index ((r*8 + b)*7 + py)*7 + px, 1024 channels contiguous
//
// R4: R2 structure (2 tiles/CTA, 8 independent LDG.128/thread) + streaming
// stores (__stcs, evict-first in L2). The image (134MB) nearly fits in L2
// (126MB) and persists across graph replays; keeping the 51MB output stream
// from evicting it converts most DRAM reads into L2 hits.

#define N_ROIS 32
#define N_BATCH 8
#define POOLP 7
#define CH 1024
#define IMG_W 64
#define IMG_H 64
#define N_TILES (N_ROIS * N_BATCH * POOLP * POOLP)   // 12544
#define HALF_TILES (N_TILES / 2)                     // 6272

struct TileAddr {
    const float4* p00;
    const float4* p01;
    const float4* p10;
    const float4* p11;
    float wx, wy;
};

__device__ __forceinline__ TileAddr tile_addr(const float* __restrict__ img,
                                              const int* __restrict__ rois,
                                              int flat)
{
    const int px = flat % POOLP;
    const int py = (flat / POOLP) % POOLP;
    const int b  = (flat / (POOLP * POOLP)) % N_BATCH;
    const int r  = flat / (POOLP * POOLP * N_BATCH);

    const int rx = rois[r * 4 + 0];
    const int ry = rois[r * 4 + 1];
    const int rw = rois[r * 4 + 2];
    const int rh = rois[r * 4 + 3];

    // coord = (p+0.5)*(size/POOL) - 0.5 (matches reference _edge)
    const float cx = ((float)px + 0.5f) * ((float)rw / (float)POOLP) - 0.5f;
    const float fx = floorf(cx);
    const int lox = max((int)fx, 0);
    const int hix = min(max((int)ceilf(cx), 0), rw - 1);
    const int x0 = rx + lox;
    const int x1 = rx + hix;

    const float cy = ((float)py + 0.5f) * ((float)rh / (float)POOLP) - 0.5f;
    const float fy = floorf(cy);
    const int loy = max((int)fy, 0);
    const int hiy = min(max((int)ceilf(cy), 0), rh - 1);
    const int y0 = ry + loy;
    const int y1 = ry + hiy;

    const size_t base_b = (size_t)b * IMG_H * IMG_W * CH;

    TileAddr ta;
    ta.p00 = (const float4*)(img + base_b + ((size_t)y0 * IMG_W + x0) * CH);
    ta.p01 = (const float4*)(img + base_b + ((size_t)y0 * IMG_W + x1) * CH);
    ta.p10 = (const float4*)(img + base_b + ((size_t)y1 * IMG_W + x0) * CH);
    ta.p11 = (const float4*)(img + base_b + ((size_t)y1 * IMG_W + x1) * CH);
    ta.wx = cx - fx;
    ta.wy = cy - fy;
    return ta;
}

__device__ __forceinline__ float4 lerp4(float4 a, float4 b, float4 c, float4 d,
                                        float wx, float wy)
{
    float4 res;
    float top, bot;
    top = a.x + (b.x - a.x) * wx;
    bot = c.x + (d.x - c.x) * wx;
    res.x = top + (bot - top) * wy;
    top = a.y + (b.y - a.y) * wx;
    bot = c.y + (d.y - c.y) * wx;
    res.y = top + (bot - top) * wy;
    top = a.z + (b.z - a.z) * wx;
    bot = c.z + (d.z - c.z) * wx;
    res.z = top + (bot - top) * wy;
    top = a.w + (b.w - a.w) * wx;
    bot = c.w + (d.w - c.w) * wx;
    res.w = top + (bot - top) * wy;
    return res;
}

__global__ void __launch_bounds__(256) roi_align_kernel_cs(
    const float* __restrict__ img,
    const int*   __restrict__ rois,
    float*       __restrict__ out)
{
    const int flat0 = blockIdx.x;
    const int flat1 = blockIdx.x + HALF_TILES;
    const int t = threadIdx.x;      // 256 threads * float4 = 1024 channels

    const TileAddr ta0 = tile_addr(img, rois, flat0);
    const TileAddr ta1 = tile_addr(img, rois, flat1);

    // Issue all 8 loads back-to-back for maximum MLP
    const float4 a0 = ta0.p00[t];
    const float4 b0 = ta0.p01[t];
    const float4 c0 = ta0.p10[t];
    const float4 d0 = ta0.p11[t];
    const float4 a1 = ta1.p00[t];
    const float4 b1 = ta1.p01[t];
    const float4 c1 = ta1.p10[t];
    const float4 d1 = ta1.p11[t];

    float4* o0 = (float4*)(out + (size_t)flat0 * CH) + t;
    float4* o1 = (float4*)(out + (size_t)flat1 * CH) + t;

    // Streaming (evict-first) stores: don't let the output stream evict the
    // image from L2 — the image persists in L2 across graph replays.
    __stcs(o0, lerp4(a0, b0, c0, d0, ta0.wx, ta0.wy));
    __stcs(o1, lerp4(a1, b1, c1, d1, ta1.wx, ta1.wy));
}

extern "C" void kernel_launch(void* const* d_in, const int* in_sizes, int n_in,
                              void* d_out, int out_size)
{
    const float* img  = (const float*)d_in[0];
    const int*   rois = (const int*)d_in[1];
    float*       out  = (float*)d_out;

    roi_align_kernel_cs<<<HALF_TILES, 256>>>(img, rois, out);
}